// round 4
// baseline (speedup 1.0000x reference)
#include <cuda_runtime.h>
#include <cuda_fp16.h>
#include <cstdint>

// Mahalanobis max-score via legacy HMMA (mma.sync m16n8k16 fp16, f32 accum).
// D[64, 88] = [F_hi | F_lo] (K-concat, A exact) @ B, where
//   B cols 0..63   = P (single fp16; error enters as tiny f dP f)
//   B cols 64+2c   = hi(muP[c]),  65+2c = lo(muP[c])  (cross exact, same thread)
//   B cols 84..87  = 0 pad
// Epilogue: qf = sum_k f32(f)[k] * D[m,k] (k<64); score_c = D_h + D_l - 0.5*qmu_c;
// out = alpha * (max_c score_c - 0.5*qf).

#define DD 64
#define CC 10
#define TM 64          // rows per CTA tile
#define NT 11          // n-tiles of 8 -> N = 88
#define NW 4           // warps per CTA

// ---------------- PTX helpers ----------------
static __device__ __forceinline__ uint32_t smem_u32(const void* p) {
    uint32_t a;
    asm("{ .reg .u64 t; cvta.to.shared.u64 t, %1; cvt.u32.u64 %0, t; }" : "=r"(a) : "l"(p));
    return a;
}
static __device__ __forceinline__ void ldsm4(uint32_t* r, uint32_t addr) {
    asm volatile("ldmatrix.sync.aligned.m8n8.x4.shared.b16 {%0,%1,%2,%3}, [%4];"
                 : "=r"(r[0]), "=r"(r[1]), "=r"(r[2]), "=r"(r[3]) : "r"(addr));
}
static __device__ __forceinline__ void ldsm2(uint32_t* r, uint32_t addr) {
    asm volatile("ldmatrix.sync.aligned.m8n8.x2.shared.b16 {%0,%1}, [%2];"
                 : "=r"(r[0]), "=r"(r[1]) : "r"(addr));
}
static __device__ __forceinline__ void mma16816(float* d, const uint32_t* a, const uint32_t* b) {
    asm volatile(
        "mma.sync.aligned.m16n8k16.row.col.f32.f16.f16.f32 "
        "{%0,%1,%2,%3}, {%4,%5,%6,%7}, {%8,%9}, {%0,%1,%2,%3};"
        : "+f"(d[0]), "+f"(d[1]), "+f"(d[2]), "+f"(d[3])
        : "r"(a[0]), "r"(a[1]), "r"(a[2]), "r"(a[3]), "r"(b[0]), "r"(b[1]));
}
static __device__ __forceinline__ uint32_t pack_h2(__half a, __half b) {
    union { __half2 h; uint32_t u; } cv;
    cv.h = __halves2half2(a, b);
    return cv.u;
}
static __device__ __forceinline__ float2 h2_to_f2(uint32_t u) {
    union { uint32_t u; __half2 h; } cv;
    cv.u = u;
    return __half22float2(cv.h);
}

// swizzle: 16B-chunk index XOR (row & 7); rows are 128B (64 fp16)
static __device__ __forceinline__ uint32_t swz(uint32_t row, uint32_t chunk) {
    return row * 128u + ((chunk ^ (row & 7u)) << 4);
}

__global__ __launch_bounds__(128)
void mahal_hmma(const float* __restrict__ features, const float* __restrict__ mu,
                const float* __restrict__ P, const float* __restrict__ alpha_p,
                float* __restrict__ out, int nTiles) {
    __shared__ __align__(16) uint8_t sAh[TM * 128];     // F hi, fp16 [64][64]
    __shared__ __align__(16) uint8_t sAl[TM * 128];     // F lo
    __shared__ __align__(16) uint8_t sB[NT * 8 * 128];  // B^T rows [88][64] fp16
    __shared__ float sMuP[CC * DD];
    __shared__ float sNegQ[16];

    const int tid = threadIdx.x;
    const int w = tid >> 5;
    const int t = tid & 31;
    const uint32_t uAh = smem_u32(sAh);
    const uint32_t uAl = smem_u32(sAl);
    const uint32_t uB  = smem_u32(sB);

    // ---------- per-CTA prep: muP (fp32), -0.5*qmu, B table (fp16) ----------
    for (int idx = tid; idx < CC * DD; idx += 128) {
        int c = idx >> 6, k = idx & 63;
        const float* mc = mu + c * DD;
        const float* pk = P + k * DD;   // P symmetric: column k == row k
        float s = 0.f;
        #pragma unroll 16
        for (int j = 0; j < DD; j++) s = fmaf(mc[j], pk[j], s);
        sMuP[idx] = s;
    }
    __syncthreads();
    if (tid < CC) {
        float q = 0.f;
        #pragma unroll 16
        for (int k = 0; k < DD; k++) q = fmaf(sMuP[tid * DD + k], mu[tid * DD + k], q);
        sNegQ[tid] = -0.5f * q;
    }
    for (int idx = tid; idx < NT * 8 * DD; idx += 128) {
        int n = idx >> 6, k = idx & 63;
        __half hv;
        if (n < DD) {
            hv = __float2half_rn(P[n * DD + k]);            // B^T[n][k] = P[k][n] = P[n][k]
        } else if (n < DD + 2 * CC) {
            int c = (n - DD) >> 1;
            float v = sMuP[c * DD + k];
            __half h = __float2half_rn(v);
            hv = ((n - DD) & 1) ? __float2half_rn(v - __half2float(h)) : h;
        } else {
            hv = __float2half_rn(0.f);
        }
        *reinterpret_cast<__half*>(sB + swz((uint32_t)n, (uint32_t)(k >> 3)) + (k & 7) * 2) = hv;
    }
    const float alpha0 = __ldg(alpha_p);
    __syncthreads();

    // ---------- precomputed ldmatrix addresses ----------
    const uint32_t lrow = 16u * w + (tid & 15);           // A frag row
    const uint32_t asel = (uint32_t)(t >> 4);             // 0: k-lo chunk, 1: k-hi
    uint32_t aOffK[4], bOffK[4];
    #pragma unroll
    for (int kk = 0; kk < 4; kk++) aOffK[kk] = swz(lrow, 2 * kk + asel);
    const uint32_t t15 = (uint32_t)(t & 15);
    const uint32_t brow0 = t15 & 7;                        // + 8*nt
    const uint32_t bsel = t15 >> 3;
    #pragma unroll
    for (int kk = 0; kk < 4; kk++) bOffK[kk] = (((2u * kk + bsel) ^ (brow0 & 7u)) << 4) + brow0 * 128u;

    const int q = t & 3;
    const uint32_t r0 = 16u * w + (uint32_t)(t >> 2);
    const uint32_t r1 = r0 + 8u;

    // ---------- main persistent loop ----------
    for (int tile = blockIdx.x; tile < nTiles; tile += gridDim.x) {
        // load tile [64 rows x 64 f32] into regs (coalesced float4)
        const float4* src = reinterpret_cast<const float4*>(features) + (size_t)tile * (TM * DD / 4);
        float4 v[8];
        #pragma unroll
        for (int i = 0; i < 8; i++) v[i] = src[i * 128 + tid];

        __syncthreads();   // prior epilogue smem reads complete

        // convert -> fp16 hi/lo -> swizzled smem
        #pragma unroll
        for (int i = 0; i < 8; i++) {
            int idx = i * 128 + tid;
            uint32_t row = (uint32_t)(idx >> 4);
            uint32_t c4  = (uint32_t)(idx & 15);
            __half hx = __float2half_rn(v[i].x), hy = __float2half_rn(v[i].y);
            __half hz = __float2half_rn(v[i].z), hw = __float2half_rn(v[i].w);
            __half lx = __float2half_rn(v[i].x - __half2float(hx));
            __half ly = __float2half_rn(v[i].y - __half2float(hy));
            __half lz = __float2half_rn(v[i].z - __half2float(hz));
            __half lw = __float2half_rn(v[i].w - __half2float(hw));
            uint32_t off = swz(row, c4 >> 1) + (c4 & 1) * 8;
            uint2 H; H.x = pack_h2(hx, hy); H.y = pack_h2(hz, hw);
            uint2 L; L.x = pack_h2(lx, ly); L.y = pack_h2(lz, lw);
            *reinterpret_cast<uint2*>(sAh + off) = H;
            *reinterpret_cast<uint2*>(sAl + off) = L;
        }
        __syncthreads();

        // ---- MMA: acc[nt] += Fhi @ B + Flo @ B ----
        float acc[NT][4];
        #pragma unroll
        for (int nt = 0; nt < NT; nt++) {
            acc[nt][0] = 0.f; acc[nt][1] = 0.f; acc[nt][2] = 0.f; acc[nt][3] = 0.f;
        }
        #pragma unroll
        for (int kk = 0; kk < 4; kk++) {
            uint32_t ah[4], al[4];
            ldsm4(ah, uAh + aOffK[kk]);
            ldsm4(al, uAl + aOffK[kk]);
            #pragma unroll
            for (int nt = 0; nt < NT; nt++) {
                uint32_t b[2];
                ldsm2(b, uB + nt * (8 * 128) + bOffK[kk]);
                mma16816(acc[nt], ah, b);
                mma16816(acc[nt], al, b);
            }
        }

        // ---- epilogue ----
        float qf0 = 0.f, qf1 = 0.f;
        #pragma unroll
        for (int nt = 0; nt < 8; nt++) {
            uint32_t o0 = swz(r0, (uint32_t)nt) + 4u * q;
            uint32_t o1 = swz(r1, (uint32_t)nt) + 4u * q;
            float2 fh0 = h2_to_f2(*reinterpret_cast<const uint32_t*>(sAh + o0));
            float2 fl0 = h2_to_f2(*reinterpret_cast<const uint32_t*>(sAl + o0));
            float2 fh1 = h2_to_f2(*reinterpret_cast<const uint32_t*>(sAh + o1));
            float2 fl1 = h2_to_f2(*reinterpret_cast<const uint32_t*>(sAl + o1));
            qf0 = fmaf(fh0.x + fl0.x, acc[nt][0], qf0);
            qf0 = fmaf(fh0.y + fl0.y, acc[nt][1], qf0);
            qf1 = fmaf(fh1.x + fl1.x, acc[nt][2], qf1);
            qf1 = fmaf(fh1.y + fl1.y, acc[nt][3], qf1);
        }
        // classes: thread q holds class q (nt8), 4+q (nt9), 8+q if q<2 (nt10)
        float s0 = acc[8][0] + acc[8][1] + sNegQ[q];
        float s1 = acc[8][2] + acc[8][3] + sNegQ[q];
        s0 = fmaxf(s0, acc[9][0] + acc[9][1] + sNegQ[4 + q]);
        s1 = fmaxf(s1, acc[9][2] + acc[9][3] + sNegQ[4 + q]);
        if (q < 2) {
            s0 = fmaxf(s0, acc[10][0] + acc[10][1] + sNegQ[8 + q]);
            s1 = fmaxf(s1, acc[10][2] + acc[10][3] + sNegQ[8 + q]);
        }
        #pragma unroll
        for (int ofs = 1; ofs <= 2; ofs <<= 1) {
            qf0 += __shfl_xor_sync(0xffffffffu, qf0, ofs);
            qf1 += __shfl_xor_sync(0xffffffffu, qf1, ofs);
            s0 = fmaxf(s0, __shfl_xor_sync(0xffffffffu, s0, ofs));
            s1 = fmaxf(s1, __shfl_xor_sync(0xffffffffu, s1, ofs));
        }
        if (q == 0) {
            float* o = out + (size_t)tile * TM;
            o[r0] = alpha0 * (s0 - 0.5f * qf0);
            o[r1] = alpha0 * (s1 - 0.5f * qf1);
        }
    }
}

extern "C" void kernel_launch(void* const* d_in, const int* in_sizes, int n_in,
                              void* d_out, int out_size) {
    const float* features = (const float*)d_in[0];
    const float* mu       = (const float*)d_in[1];
    const float* P        = (const float*)d_in[2];
    const float* alpha    = (const float*)d_in[3];
    float* out = (float*)d_out;

    int n = in_sizes[0] / DD;
    int nTiles = n / TM;

    int grid = 148 * 6;
    if (grid > nTiles) grid = nTiles;
    mahal_hmma<<<grid, 128>>>(features, mu, P, alpha, out, nTiles);
}

// round 6
// speedup vs baseline: 1.4090x; 1.4090x over previous
#include <cuda_runtime.h>
#include <cuda_fp16.h>
#include <cstdint>
#include <math_constants.h>

// Mahalanobis max-score, all-register HMMA version.
// Per 16-row tile (one warp): D[16, 88] = [F_hi | F_lo] @ B  via mma.m16n8k16,
// A fragments loaded straight from gmem (no smem), B fragments persistent in
// registers (built once), qf epilogue paired from registers.
//   B cols 0..63  = P (fp16)
//   B cols 64+2c / 65+2c = hi/lo fp16 of muP[c] (cross term exact, same thread)
//   B cols 84..87 = 0
// out[m] = alpha * (max_c (D_hi+D_lo - 0.5 qmu_c) - 0.5 * sum_k f[k] D[m,k])

#define DD 64
#define CC 10

static __device__ __forceinline__ void mma16816(float* d, const uint32_t* a, const uint32_t* b) {
    asm volatile(
        "mma.sync.aligned.m16n8k16.row.col.f32.f16.f16.f32 "
        "{%0,%1,%2,%3}, {%4,%5,%6,%7}, {%8,%9}, {%0,%1,%2,%3};"
        : "+f"(d[0]), "+f"(d[1]), "+f"(d[2]), "+f"(d[3])
        : "r"(a[0]), "r"(a[1]), "r"(a[2]), "r"(a[3]), "r"(b[0]), "r"(b[1]));
}
static __device__ __forceinline__ uint32_t pack_h2(__half a, __half b) {
    union { __half2 h; uint32_t u; } cv;
    cv.h = __halves2half2(a, b);
    return cv.u;
}
static __device__ __forceinline__ float2 h2f(uint32_t u) {
    union { uint32_t u; __half2 h; } cv;
    cv.u = u;
    return __half22float2(cv.h);
}
// split a float2 into packed fp16 hi and lo halves (hi+lo == f exactly to ~2^-22)
static __device__ __forceinline__ void split2(float2 v, uint32_t& h, uint32_t& l) {
    __half2 hh = __float22half2_rn(v);
    float2 hf = __half22float2(hh);
    __half2 ll = __float22half2_rn(make_float2(v.x - hf.x, v.y - hf.y));
    union { __half2 h; uint32_t u; } a, b;
    a.h = hh; b.h = ll;
    h = a.u; l = b.u;
}
static __device__ __forceinline__ __half muphalf(float v, bool lo) {
    __half h = __float2half_rn(v);
    return lo ? __float2half_rn(v - __half2float(h)) : h;
}

__global__ __launch_bounds__(128, 2)
void mahal_reg(const float* __restrict__ F, const float* __restrict__ mu,
               const float* __restrict__ P, const float* __restrict__ alpha_p,
               float* __restrict__ out, int nTiles16) {
    __shared__ float sMuP[CC * DD];
    __shared__ float sNegQ[16];

    const int tid = threadIdx.x;

    // ---- one-time prep: muP (fp32), -0.5*qmu ----
    for (int idx = tid; idx < CC * DD; idx += 128) {
        int c = idx >> 6, k = idx & 63;
        const float* mc = mu + c * DD;
        const float* pk = P + k * DD;       // P symmetric
        float s = 0.f;
        #pragma unroll 16
        for (int j = 0; j < DD; j++) s = fmaf(mc[j], pk[j], s);
        sMuP[idx] = s;
    }
    __syncthreads();
    if (tid < 16) {
        float v = 0.f;
        if (tid < CC) {
            float qq = 0.f;
            #pragma unroll 16
            for (int k = 0; k < DD; k++) qq = fmaf(sMuP[tid * DD + k], mu[tid * DD + k], qq);
            v = -0.5f * qq;
        }
        sNegQ[tid] = v;
    }
    __syncthreads();

    const int t  = tid & 31;
    const int q  = t & 3;        // threadID_in_group
    const int tq = t >> 2;       // groupID (row / n index)

    // ---- build persistent B fragments in registers ----
    // b-frag layout (m16n8k16 row.col): b0 = B[2q][n],B[2q+1][n]; b1 = B[2q+8][n],B[2q+9][n]
    uint32_t Bf[4][11][2];
    #pragma unroll
    for (int kk = 0; kk < 4; kk++) {
        #pragma unroll
        for (int nt = 0; nt < 11; nt++) {
            int n = 8 * nt + tq;
            int k0 = 16 * kk + 2 * q;
            uint32_t b0, b1;
            if (n < DD) {
                b0 = pack_h2(__float2half_rn(P[(k0    ) * DD + n]),
                             __float2half_rn(P[(k0 + 1) * DD + n]));
                b1 = pack_h2(__float2half_rn(P[(k0 + 8) * DD + n]),
                             __float2half_rn(P[(k0 + 9) * DD + n]));
            } else if (n < DD + 2 * CC) {
                int c = (n - DD) >> 1;
                bool lo = (n - DD) & 1;
                const float* mp = sMuP + c * DD;
                b0 = pack_h2(muphalf(mp[k0], lo),     muphalf(mp[k0 + 1], lo));
                b1 = pack_h2(muphalf(mp[k0 + 8], lo), muphalf(mp[k0 + 9], lo));
            } else {
                b0 = 0u; b1 = 0u;
            }
            Bf[kk][nt][0] = b0;
            Bf[kk][nt][1] = b1;
        }
    }

    const float alpha0 = __ldg(alpha_p);
    const float nq0 = sNegQ[q];
    const float nq1 = sNegQ[4 + q];
    const float nq2 = (q < 2) ? sNegQ[8 + q] : -CUDART_INF_F;

    const int gw = blockIdx.x * 4 + (tid >> 5);
    const int stride = gridDim.x * 4;

    for (int tile = gw; tile < nTiles16; tile += stride) {
        const float2* base = reinterpret_cast<const float2*>(F) + (size_t)tile * 512;

        // ---- load A fragments directly from gmem, split fp16 hi/lo ----
        // a-frag: a0=(r,2q..2q+1) a1=(r+8,..) a2=(r,2q+8..) a3=(r+8,2q+8..); r = tq
        uint32_t Ah[4][4], Al[4][4];
        #pragma unroll
        for (int kk = 0; kk < 4; kk++) {
            int kc = (16 * kk + 2 * q) >> 1;             // float2 index of k pair
            float2 v0 = base[tq * 32 + kc];
            float2 v1 = base[(tq + 8) * 32 + kc];
            float2 v2 = base[tq * 32 + kc + 4];
            float2 v3 = base[(tq + 8) * 32 + kc + 4];
            split2(v0, Ah[kk][0], Al[kk][0]);
            split2(v1, Ah[kk][1], Al[kk][1]);
            split2(v2, Ah[kk][2], Al[kk][2]);
            split2(v3, Ah[kk][3], Al[kk][3]);
        }

        // ---- MMA: acc[nt] = Fhi @ B + Flo @ B ----
        float acc[11][4];
        #pragma unroll
        for (int nt = 0; nt < 11; nt++) {
            acc[nt][0] = 0.f; acc[nt][1] = 0.f; acc[nt][2] = 0.f; acc[nt][3] = 0.f;
        }
        #pragma unroll
        for (int kk = 0; kk < 4; kk++) {
            #pragma unroll
            for (int nt = 0; nt < 11; nt++) {
                mma16816(acc[nt], Ah[kk], Bf[kk][nt]);
                mma16816(acc[nt], Al[kk], Bf[kk][nt]);
            }
        }

        // ---- epilogue: qf from registers (D col 8nt+2q pairs with A-frag k) ----
        float qf0 = 0.f, qf1 = 0.f;
        #pragma unroll
        for (int nt = 0; nt < 8; nt++) {
            int kk = nt >> 1;
            int i0 = (nt & 1) ? 2 : 0;
            float2 h0 = h2f(Ah[kk][i0]),     l0 = h2f(Al[kk][i0]);
            float2 h1 = h2f(Ah[kk][i0 + 1]), l1 = h2f(Al[kk][i0 + 1]);
            qf0 = fmaf(h0.x + l0.x, acc[nt][0], qf0);
            qf0 = fmaf(h0.y + l0.y, acc[nt][1], qf0);
            qf1 = fmaf(h1.x + l1.x, acc[nt][2], qf1);
            qf1 = fmaf(h1.y + l1.y, acc[nt][3], qf1);
        }
        // class scores: thread q holds class q (nt8), 4+q (nt9), 8+q (nt10, q<2)
        float s0 = acc[8][0] + acc[8][1] + nq0;
        float s1 = acc[8][2] + acc[8][3] + nq0;
        s0 = fmaxf(s0, acc[9][0] + acc[9][1] + nq1);
        s1 = fmaxf(s1, acc[9][2] + acc[9][3] + nq1);
        s0 = fmaxf(s0, acc[10][0] + acc[10][1] + nq2);
        s1 = fmaxf(s1, acc[10][2] + acc[10][3] + nq2);

        #pragma unroll
        for (int o = 1; o <= 2; o <<= 1) {
            qf0 += __shfl_xor_sync(0xffffffffu, qf0, o);
            qf1 += __shfl_xor_sync(0xffffffffu, qf1, o);
            s0 = fmaxf(s0, __shfl_xor_sync(0xffffffffu, s0, o));
            s1 = fmaxf(s1, __shfl_xor_sync(0xffffffffu, s1, o));
        }
        if (q == 0) {
            float* o = out + (size_t)tile * 16;
            o[tq]     = alpha0 * (s0 - 0.5f * qf0);
            o[tq + 8] = alpha0 * (s1 - 0.5f * qf1);
        }
    }
}

extern "C" void kernel_launch(void* const* d_in, const int* in_sizes, int n_in,
                              void* d_out, int out_size) {
    const float* features = (const float*)d_in[0];
    const float* mu       = (const float*)d_in[1];
    const float* P        = (const float*)d_in[2];
    const float* alpha    = (const float*)d_in[3];
    float* out = (float*)d_out;

    int n = in_sizes[0] / DD;
    int nTiles16 = n / 16;

    int grid = 296;                      // 2 CTAs/SM x 148, all resident
    mahal_reg<<<grid, 128>>>(features, mu, P, alpha, out, nTiles16);
}